// round 11
// baseline (speedup 1.0000x reference)
#include <cuda_runtime.h>
#include <math.h>
#include <stdint.h>

// Problem constants
#define BB 4
#define NN 2048
#define CC 1152
#define HH 16
#define DH 72
#define HALF 36
#define MROWS (BB * NN)          // 8192
#define QKVD  (3 * CC)           // 3456

// ---------------------------------------------------------------------------
// Scratch (device globals; no runtime allocation allowed)
// ---------------------------------------------------------------------------
__device__ float g_qkv[(size_t)MROWS * QKVD];            // [b*n][3456]
__device__ float g_q[(size_t)BB * HH * NN * DH];         // [b][h][n][dh]
__device__ float g_k[(size_t)BB * HH * NN * DH];
__device__ float g_v[(size_t)BB * HH * NN * DH];
__device__ float g_ctx[(size_t)MROWS * CC];              // [b*n][h*dh]

// ---------------------------------------------------------------------------
// GEMM: C[m][n] = sum_k A[m][k] * B[n][k]  (+ bias[n])
// A: MxK row-major, B: NxK row-major (both K contiguous -> NT gemm)
// 128x128 tile, BK=16, 256 threads, 8x8 per thread.
// M % 128 == 0, N % 128 == 0, K % 16 == 0 guaranteed by problem dims.
// ---------------------------------------------------------------------------
__global__ __launch_bounds__(256, 2)
void gemm_nt(const float* __restrict__ A, const float* __restrict__ B,
             const float* __restrict__ bias, float* __restrict__ C,
             int M, int Nc, int K)
{
    __shared__ float As[16][132];
    __shared__ float Bs[16][132];

    const int tid = threadIdx.x;
    const int bm = blockIdx.y * 128;
    const int bn = blockIdx.x * 128;
    const int tx = tid & 15;    // 16 col groups
    const int ty = tid >> 4;    // 16 row groups

    // loader mapping: 512 float4 per 128x16 tile; thread loads f=tid and f=tid+256
    const int lr = tid >> 2;            // 0..63
    const int lk = (tid & 3) * 4;       // 0,4,8,12

    const float* Ap0 = A + (size_t)(bm + lr) * K + lk;
    const float* Ap1 = A + (size_t)(bm + lr + 64) * K + lk;
    const float* Bp0 = B + (size_t)(bn + lr) * K + lk;
    const float* Bp1 = B + (size_t)(bn + lr + 64) * K + lk;

    float acc[8][8];
#pragma unroll
    for (int i = 0; i < 8; i++)
#pragma unroll
        for (int j = 0; j < 8; j++) acc[i][j] = 0.f;

    for (int k0 = 0; k0 < K; k0 += 16) {
        float4 a0 = *(const float4*)(Ap0 + k0);
        float4 a1 = *(const float4*)(Ap1 + k0);
        float4 b0 = *(const float4*)(Bp0 + k0);
        float4 b1 = *(const float4*)(Bp1 + k0);

        __syncthreads();
        As[lk + 0][lr] = a0.x; As[lk + 1][lr] = a0.y;
        As[lk + 2][lr] = a0.z; As[lk + 3][lr] = a0.w;
        As[lk + 0][lr + 64] = a1.x; As[lk + 1][lr + 64] = a1.y;
        As[lk + 2][lr + 64] = a1.z; As[lk + 3][lr + 64] = a1.w;
        Bs[lk + 0][lr] = b0.x; Bs[lk + 1][lr] = b0.y;
        Bs[lk + 2][lr] = b0.z; Bs[lk + 3][lr] = b0.w;
        Bs[lk + 0][lr + 64] = b1.x; Bs[lk + 1][lr + 64] = b1.y;
        Bs[lk + 2][lr + 64] = b1.z; Bs[lk + 3][lr + 64] = b1.w;
        __syncthreads();

#pragma unroll
        for (int kk = 0; kk < 16; kk++) {
            float ar[8], br[8];
            *(float4*)(ar)     = *(const float4*)&As[kk][ty * 8];
            *(float4*)(ar + 4) = *(const float4*)&As[kk][ty * 8 + 4];
            *(float4*)(br)     = *(const float4*)&Bs[kk][tx * 8];
            *(float4*)(br + 4) = *(const float4*)&Bs[kk][tx * 8 + 4];
#pragma unroll
            for (int i = 0; i < 8; i++)
#pragma unroll
                for (int j = 0; j < 8; j++)
                    acc[i][j] = fmaf(ar[i], br[j], acc[i][j]);
        }
    }

    float bv[8];
#pragma unroll
    for (int j = 0; j < 8; j++)
        bv[j] = bias ? bias[bn + tx * 8 + j] : 0.f;

#pragma unroll
    for (int i = 0; i < 8; i++) {
        float* crow = C + (size_t)(bm + ty * 8 + i) * Nc + bn + tx * 8;
        float4 o0, o1;
        o0.x = acc[i][0] + bv[0]; o0.y = acc[i][1] + bv[1];
        o0.z = acc[i][2] + bv[2]; o0.w = acc[i][3] + bv[3];
        o1.x = acc[i][4] + bv[4]; o1.y = acc[i][5] + bv[5];
        o1.z = acc[i][6] + bv[6]; o1.w = acc[i][7] + bv[7];
        *(float4*)(crow)     = o0;
        *(float4*)(crow + 4) = o1;
    }
}

// ---------------------------------------------------------------------------
// RoPE + RMSNorm on q,k, plus split/transpose of q,k,v into [b][h][n][dh].
// One warp per row; total rows = 3*B*H*N. Row order: s (q/k/v) slowest.
// ---------------------------------------------------------------------------
__global__ __launch_bounds__(256)
void rope_norm_split(const float* __restrict__ qkv,
                     const float* __restrict__ qw, const float* __restrict__ kw,
                     float* __restrict__ q, float* __restrict__ k, float* __restrict__ v)
{
    int gid  = blockIdx.x * 8 + (threadIdx.x >> 5);
    int lane = threadIdx.x & 31;

    int n = gid & (NN - 1);
    int t = gid >> 11;           // / 2048
    int h = t & (HH - 1);
    t >>= 4;
    int b = t & (BB - 1);
    int s = t >> 2;              // 0=q 1=k 2=v

    const float* src = qkv + (size_t)(b * NN + n) * QKVD + (s * HH + h) * DH;
    float* dstbase = (s == 0) ? g_q : (s == 1) ? g_k : g_v;
    float* dst = dstbase + (size_t)((b * HH + h) * NN + n) * DH;
    (void)q; (void)k; (void)v;

    if (s == 2) {
        for (int i = lane; i < DH; i += 32) dst[i] = src[i];
        return;
    }

    const float* w = (s == 0) ? qw : kw;

    float a0, c0v, a1 = 0.f, c1v = 0.f;
    float ss = 0.f;

    // pair p = lane (0..31)
    {
        int p = lane;
        float x1 = src[p], x2 = src[p + HALF];
        float inv = powf(10000.0f, -(float)p * (1.0f / HALF));
        float ang = (float)n * inv;
        float sv, cv;
        sincosf(ang, &sv, &cv);
        a0  = x1 * cv - x2 * sv;
        c0v = x2 * cv + x1 * sv;
        ss  = a0 * a0 + c0v * c0v;
    }
    // pair p = lane + 32 (lanes 0..3)
    if (lane < HALF - 32) {
        int p = lane + 32;
        float x1 = src[p], x2 = src[p + HALF];
        float inv = powf(10000.0f, -(float)p * (1.0f / HALF));
        float ang = (float)n * inv;
        float sv, cv;
        sincosf(ang, &sv, &cv);
        a1  = x1 * cv - x2 * sv;
        c1v = x2 * cv + x1 * sv;
        ss += a1 * a1 + c1v * c1v;
    }

#pragma unroll
    for (int off = 16; off > 0; off >>= 1)
        ss += __shfl_xor_sync(0xffffffffu, ss, off);

    float r = rsqrtf(ss * (1.0f / DH) + 1e-6f);

    dst[lane]        = w[lane] * a0 * r;
    dst[lane + HALF] = w[lane + HALF] * c0v * r;
    if (lane < HALF - 32) {
        dst[lane + 32]        = w[lane + 32] * a1 * r;
        dst[lane + 32 + HALF] = w[lane + 32 + HALF] * c1v * r;
    }
}

// ---------------------------------------------------------------------------
// Flash attention per (b,h): Bq=64 queries per block, loop over Bk=64 kv tiles.
// 256 threads: thread t -> rows {2*(t/8), 2*(t/8)+1}; QK cols (t%8)*8..+7,
// PV cols (t%8)*9..+8. Online softmax. Output written in [b][n][h][dh] layout.
// ---------------------------------------------------------------------------
#define ATTN_SMEM_FLOATS (64*73 + 64*73 + 64*72 + 64*65)

__global__ __launch_bounds__(256)
void attn_kernel(const float* __restrict__ Q, const float* __restrict__ K,
                 const float* __restrict__ V, float* __restrict__ O)
{
    extern __shared__ float sm[];
    float* Qs = sm;                 // [64][73]
    float* Ks = Qs + 64 * 73;       // [64][73]
    float* Vs = Ks + 64 * 73;       // [64][72]
    float* Ss = Vs + 64 * 72;       // [64][65]

    const int tid = threadIdx.x;
    const int bh = blockIdx.y;                  // b*H + h
    const int q0 = blockIdx.x * 64;
    const size_t base = (size_t)bh * NN * DH;

    const float scale = 0.11785113019775793f;   // 72^-0.5

    // load + pre-scale Q tile
    for (int idx = tid; idx < 64 * DH; idx += 256) {
        int r = idx / DH, c = idx - r * DH;
        Qs[r * 73 + c] = Q[base + (size_t)(q0 + r) * DH + c] * scale;
    }

    const int rp = tid >> 3;        // 0..31
    const int cg = tid & 7;         // 0..7
    const int r0 = rp * 2;
    const int j0 = cg * 8;
    const int c0 = cg * 9;

    float m0 = -1e30f, m1 = -1e30f, l0 = 0.f, l1 = 0.f;
    float acc0[9], acc1[9];
#pragma unroll
    for (int c = 0; c < 9; c++) { acc0[c] = 0.f; acc1[c] = 0.f; }

    for (int kt = 0; kt < NN / 64; kt++) {
        __syncthreads();
        for (int idx = tid; idx < 64 * DH; idx += 256) {
            int r = idx / DH, c = idx - r * DH;
            size_t g = base + (size_t)(kt * 64 + r) * DH + c;
            Ks[r * 73 + c] = K[g];
            Vs[r * 72 + c] = V[g];
        }
        __syncthreads();

        // S = Q K^T (scaled)
        float s0[8], s1[8];
#pragma unroll
        for (int jj = 0; jj < 8; jj++) { s0[jj] = 0.f; s1[jj] = 0.f; }
#pragma unroll 4
        for (int d = 0; d < DH; d++) {
            float qa = Qs[r0 * 73 + d];
            float qb = Qs[(r0 + 1) * 73 + d];
#pragma unroll
            for (int jj = 0; jj < 8; jj++) {
                float kv = Ks[(j0 + jj) * 73 + d];
                s0[jj] = fmaf(qa, kv, s0[jj]);
                s1[jj] = fmaf(qb, kv, s1[jj]);
            }
        }

        // tile row max
        float tm0 = s0[0], tm1 = s1[0];
#pragma unroll
        for (int jj = 1; jj < 8; jj++) { tm0 = fmaxf(tm0, s0[jj]); tm1 = fmaxf(tm1, s1[jj]); }
#pragma unroll
        for (int off = 1; off < 8; off <<= 1) {
            tm0 = fmaxf(tm0, __shfl_xor_sync(0xffffffffu, tm0, off));
            tm1 = fmaxf(tm1, __shfl_xor_sync(0xffffffffu, tm1, off));
        }
        float mn0 = fmaxf(m0, tm0), mn1 = fmaxf(m1, tm1);
        float al0 = __expf(m0 - mn0), al1 = __expf(m1 - mn1);
        m0 = mn0; m1 = mn1;

        float sum0 = 0.f, sum1 = 0.f;
#pragma unroll
        for (int jj = 0; jj < 8; jj++) {
            s0[jj] = __expf(s0[jj] - mn0);
            s1[jj] = __expf(s1[jj] - mn1);
            sum0 += s0[jj]; sum1 += s1[jj];
        }
#pragma unroll
        for (int off = 1; off < 8; off <<= 1) {
            sum0 += __shfl_xor_sync(0xffffffffu, sum0, off);
            sum1 += __shfl_xor_sync(0xffffffffu, sum1, off);
        }
        l0 = l0 * al0 + sum0;
        l1 = l1 * al1 + sum1;
#pragma unroll
        for (int c = 0; c < 9; c++) { acc0[c] *= al0; acc1[c] *= al1; }

#pragma unroll
        for (int jj = 0; jj < 8; jj++) {
            Ss[r0 * 65 + j0 + jj]       = s0[jj];
            Ss[(r0 + 1) * 65 + j0 + jj] = s1[jj];
        }
        __syncthreads();

        // acc += P @ V
#pragma unroll 2
        for (int j = 0; j < 64; j++) {
            float p0 = Ss[r0 * 65 + j];
            float p1 = Ss[(r0 + 1) * 65 + j];
#pragma unroll
            for (int c = 0; c < 9; c++) {
                float vv = Vs[j * 72 + c0 + c];
                acc0[c] = fmaf(p0, vv, acc0[c]);
                acc1[c] = fmaf(p1, vv, acc1[c]);
            }
        }
    }

    float inv0 = 1.f / l0, inv1 = 1.f / l1;
    int b = bh >> 4, h = bh & 15;
    size_t orow0 = ((size_t)(b * NN + q0 + r0) * HH + h) * DH + c0;
    size_t orow1 = orow0 + (size_t)HH * DH;
#pragma unroll
    for (int c = 0; c < 9; c++) {
        O[orow0 + c] = acc0[c] * inv0;
        O[orow1 + c] = acc1[c] * inv1;
    }
}

// ---------------------------------------------------------------------------
// launch
// ---------------------------------------------------------------------------
extern "C" void kernel_launch(void* const* d_in, const int* in_sizes, int n_in,
                              void* d_out, int out_size)
{
    const float* x      = (const float*)d_in[0];
    const float* w_qkv  = (const float*)d_in[1];
    const float* w_proj = (const float*)d_in[2];
    const float* b_proj = (const float*)d_in[3];
    const float* qw     = (const float*)d_in[4];
    const float* kw     = (const float*)d_in[5];
    float* out          = (float*)d_out;

    void *p_qkv, *p_q, *p_k, *p_v, *p_ctx;
    cudaGetSymbolAddress(&p_qkv, g_qkv);
    cudaGetSymbolAddress(&p_q, g_q);
    cudaGetSymbolAddress(&p_k, g_k);
    cudaGetSymbolAddress(&p_v, g_v);
    cudaGetSymbolAddress(&p_ctx, g_ctx);
    float* qkv = (float*)p_qkv;
    float* q   = (float*)p_q;
    float* k   = (float*)p_k;
    float* v   = (float*)p_v;
    float* ctx = (float*)p_ctx;

    // 1) QKV GEMM: [8192,1152] x [3456,1152]^T -> [8192,3456]
    {
        dim3 grid(QKVD / 128, MROWS / 128);
        gemm_nt<<<grid, 256>>>(x, w_qkv, nullptr, qkv, MROWS, QKVD, CC);
    }

    // 2) RoPE + RMSNorm + split to [b][h][n][dh]
    {
        int total_warps = 3 * BB * HH * NN;   // 393216
        rope_norm_split<<<total_warps / 8, 256>>>(qkv, qw, kw, q, k, v);
    }

    // 3) Flash attention -> ctx in [b][n][h*dh]
    {
        int smem = ATTN_SMEM_FLOATS * sizeof(float);
        cudaFuncSetAttribute(attn_kernel, cudaFuncAttributeMaxDynamicSharedMemorySize, smem);
        dim3 grid(NN / 64, BB * HH);
        attn_kernel<<<grid, 256, smem>>>(q, k, v, ctx);
    }

    // 4) Output projection: [8192,1152] x [1152,1152]^T + bias -> out
    {
        dim3 grid(CC / 128, MROWS / 128);
        gemm_nt<<<grid, 256>>>(ctx, w_proj, b_proj, out, MROWS, CC, CC);
    }
}

// round 16
// speedup vs baseline: 1.4542x; 1.4542x over previous
#include <cuda_runtime.h>
#include <math.h>
#include <stdint.h>

// Problem constants
#define BB 4
#define NN 2048
#define CC 1152
#define HH 16
#define DH 72
#define HALF 36
#define MROWS (BB * NN)          // 8192
#define QKVD  (3 * CC)           // 3456

// ---------------------------------------------------------------------------
// Scratch (device globals; no runtime allocation allowed)
// ---------------------------------------------------------------------------
__device__ float g_qkv[(size_t)MROWS * QKVD];            // [b*n][3456]
__device__ float g_q[(size_t)BB * HH * DH * NN];         // [b][h][dh][n]  (d-major!)
__device__ float g_k[(size_t)BB * HH * DH * NN];         // [b][h][dh][n]  (d-major!)
__device__ float g_v[(size_t)BB * HH * NN * DH];         // [b][h][n][dh]
__device__ float g_ctx[(size_t)MROWS * CC];              // [b*n][h*dh]

// ---------------------------------------------------------------------------
// GEMM: C[m][n] = sum_k A[m][k] * B[n][k]  (+ bias[n])   (unchanged, proven)
// ---------------------------------------------------------------------------
__global__ __launch_bounds__(256, 2)
void gemm_nt(const float* __restrict__ A, const float* __restrict__ B,
             const float* __restrict__ bias, float* __restrict__ C,
             int M, int Nc, int K)
{
    __shared__ float As[16][132];
    __shared__ float Bs[16][132];

    const int tid = threadIdx.x;
    const int bm = blockIdx.y * 128;
    const int bn = blockIdx.x * 128;
    const int tx = tid & 15;
    const int ty = tid >> 4;

    const int lr = tid >> 2;
    const int lk = (tid & 3) * 4;

    const float* Ap0 = A + (size_t)(bm + lr) * K + lk;
    const float* Ap1 = A + (size_t)(bm + lr + 64) * K + lk;
    const float* Bp0 = B + (size_t)(bn + lr) * K + lk;
    const float* Bp1 = B + (size_t)(bn + lr + 64) * K + lk;

    float acc[8][8];
#pragma unroll
    for (int i = 0; i < 8; i++)
#pragma unroll
        for (int j = 0; j < 8; j++) acc[i][j] = 0.f;

    for (int k0 = 0; k0 < K; k0 += 16) {
        float4 a0 = *(const float4*)(Ap0 + k0);
        float4 a1 = *(const float4*)(Ap1 + k0);
        float4 b0 = *(const float4*)(Bp0 + k0);
        float4 b1 = *(const float4*)(Bp1 + k0);

        __syncthreads();
        As[lk + 0][lr] = a0.x; As[lk + 1][lr] = a0.y;
        As[lk + 2][lr] = a0.z; As[lk + 3][lr] = a0.w;
        As[lk + 0][lr + 64] = a1.x; As[lk + 1][lr + 64] = a1.y;
        As[lk + 2][lr + 64] = a1.z; As[lk + 3][lr + 64] = a1.w;
        Bs[lk + 0][lr] = b0.x; Bs[lk + 1][lr] = b0.y;
        Bs[lk + 2][lr] = b0.z; Bs[lk + 3][lr] = b0.w;
        Bs[lk + 0][lr + 64] = b1.x; Bs[lk + 1][lr + 64] = b1.y;
        Bs[lk + 2][lr + 64] = b1.z; Bs[lk + 3][lr + 64] = b1.w;
        __syncthreads();

#pragma unroll
        for (int kk = 0; kk < 16; kk++) {
            float ar[8], br[8];
            *(float4*)(ar)     = *(const float4*)&As[kk][ty * 8];
            *(float4*)(ar + 4) = *(const float4*)&As[kk][ty * 8 + 4];
            *(float4*)(br)     = *(const float4*)&Bs[kk][tx * 8];
            *(float4*)(br + 4) = *(const float4*)&Bs[kk][tx * 8 + 4];
#pragma unroll
            for (int i = 0; i < 8; i++)
#pragma unroll
                for (int j = 0; j < 8; j++)
                    acc[i][j] = fmaf(ar[i], br[j], acc[i][j]);
        }
    }

    float bv[8];
#pragma unroll
    for (int j = 0; j < 8; j++)
        bv[j] = bias ? bias[bn + tx * 8 + j] : 0.f;

#pragma unroll
    for (int i = 0; i < 8; i++) {
        float* crow = C + (size_t)(bm + ty * 8 + i) * Nc + bn + tx * 8;
        float4 o0, o1;
        o0.x = acc[i][0] + bv[0]; o0.y = acc[i][1] + bv[1];
        o0.z = acc[i][2] + bv[2]; o0.w = acc[i][3] + bv[3];
        o1.x = acc[i][4] + bv[4]; o1.y = acc[i][5] + bv[5];
        o1.z = acc[i][6] + bv[6]; o1.w = acc[i][7] + bv[7];
        *(float4*)(crow)     = o0;
        *(float4*)(crow + 4) = o1;
    }
}

// ---------------------------------------------------------------------------
// RoPE + RMSNorm for q,k, writing d-major [b][h][dh][n] via smem transpose.
// One block = one (s in {q,k}, b, h, 32 consecutive n). 8 warps, each warp
// does 4 n-rows; results staged in sm[72][33]; coalesced 128B writes.
// ---------------------------------------------------------------------------
__global__ __launch_bounds__(256)
void rope_norm_qk(const float* __restrict__ qkv,
                  const float* __restrict__ qw, const float* __restrict__ kw)
{
    __shared__ float sm[72 * 33];
    const int tid  = threadIdx.x;
    const int w    = tid >> 5;
    const int lane = tid & 31;
    const int s    = blockIdx.z;          // 0=q, 1=k
    const int bh   = blockIdx.y;
    const int b    = bh >> 4, h = bh & 15;
    const int n0   = blockIdx.x * 32;

    const float* wgt = s ? kw : qw;
    float* dst = (s ? g_k : g_q) + (size_t)bh * DH * NN;

#pragma unroll 1
    for (int rr = 0; rr < 4; rr++) {
        int nn = rr * 8 + w;
        int n  = n0 + nn;
        const float* src = qkv + (size_t)(b * NN + n) * QKVD + (s * HH + h) * DH;

        float a0, c0v, a1 = 0.f, c1v = 0.f;
        float ss = 0.f;
        {
            int p = lane;
            float x1 = src[p], x2 = src[p + HALF];
            float inv = powf(10000.0f, -(float)p * (1.0f / HALF));
            float ang = (float)n * inv;
            float sv, cv;
            sincosf(ang, &sv, &cv);
            a0  = x1 * cv - x2 * sv;
            c0v = x2 * cv + x1 * sv;
            ss  = a0 * a0 + c0v * c0v;
        }
        if (lane < HALF - 32) {
            int p = lane + 32;
            float x1 = src[p], x2 = src[p + HALF];
            float inv = powf(10000.0f, -(float)p * (1.0f / HALF));
            float ang = (float)n * inv;
            float sv, cv;
            sincosf(ang, &sv, &cv);
            a1  = x1 * cv - x2 * sv;
            c1v = x2 * cv + x1 * sv;
            ss += a1 * a1 + c1v * c1v;
        }

#pragma unroll
        for (int off = 16; off > 0; off >>= 1)
            ss += __shfl_xor_sync(0xffffffffu, ss, off);

        float r = rsqrtf(ss * (1.0f / DH) + 1e-6f);

        sm[lane * 33 + nn]          = wgt[lane] * a0 * r;
        sm[(lane + HALF) * 33 + nn] = wgt[lane + HALF] * c0v * r;
        if (lane < HALF - 32) {
            sm[(lane + 32) * 33 + nn]        = wgt[lane + 32] * a1 * r;
            sm[(lane + 32 + HALF) * 33 + nn] = wgt[lane + 32 + HALF] * c1v * r;
        }
    }
    __syncthreads();

    // transpose out: 72 d-rows x 32 n, 128B coalesced per warp-instruction
    for (int idx = tid; idx < DH * 32; idx += 256) {
        int d = idx >> 5, nn = idx & 31;
        dst[(size_t)d * NN + n0 + nn] = sm[d * 33 + nn];
    }
}

// ---------------------------------------------------------------------------
// V split/copy (layout unchanged: [b][h][n][dh]); one warp per row.
// ---------------------------------------------------------------------------
__global__ __launch_bounds__(256)
void v_split(const float* __restrict__ qkv)
{
    int gid  = blockIdx.x * 8 + (threadIdx.x >> 5);
    int lane = threadIdx.x & 31;
    int n  = gid & (NN - 1);
    int bh = gid >> 11;
    int b  = bh >> 4, h = bh & 15;

    const float* src = qkv + (size_t)(b * NN + n) * QKVD + (2 * HH + h) * DH;
    float* dst = g_v + ((size_t)bh * NN + n) * DH;
    for (int i = lane; i < DH; i += 32) dst[i] = src[i];
}

// ---------------------------------------------------------------------------
// Flash attention v3: Bq=Bk=128, 256 threads, gemm-style 8x8 QK microtiles.
// Q,K arrive d-major from gmem -> smem [72][132]: aligned float4 on both the
// gmem load and the smem store (consecutive addresses, conflict-free), and
// aligned float4 reads in the QK loop (132 % 4 == 0), same pattern as gemm_nt.
// ---------------------------------------------------------------------------
#define AQ_S 132
#define AV_S 81
#define AS_S 132
#define ATTN3_SMEM_FLOATS (2 * DH * AQ_S + 128 * AV_S + 128 * AS_S)

__global__ __launch_bounds__(256, 1)
void attn_kernel3(const float* __restrict__ Q, const float* __restrict__ K,
                  const float* __restrict__ V, float* __restrict__ O)
{
    extern __shared__ float sm[];
    float* Qs = sm;                     // [72][132]  (d-major)
    float* Ks = Qs + DH * AQ_S;         // [72][132]  (d-major)
    float* Vs = Ks + DH * AQ_S;         // [128][81]  (row-major, cols 72..80 = 0)
    float* Ss = Vs + 128 * AV_S;        // [128][132] (row-major P)

    const int tid = threadIdx.x;
    const int tx  = tid & 15;
    const int ty  = tid >> 4;
    const int bh  = blockIdx.y;                 // b*H + h
    const int q0  = blockIdx.x * 128;
    const size_t base_t = (size_t)bh * DH * NN; // Q/K d-major base
    const size_t base_v = (size_t)bh * NN * DH; // V row-major base
    const float scale = 0.11785113019775793f;   // 72^-0.5

    // zero V pad columns once (tile loads only touch cols < 72)
    for (int r = tid; r < 128; r += 256) {
#pragma unroll
        for (int c = DH; c < AV_S; c++) Vs[r * AV_S + c] = 0.f;
    }

    // load Q tile (d-major, float4 both sides) + pre-scale
    for (int idx = tid; idx < DH * 32; idx += 256) {
        int d = idx >> 5, r4 = idx & 31;
        float4 v = *(const float4*)(Q + base_t + (size_t)d * NN + q0 + r4 * 4);
        v.x *= scale; v.y *= scale; v.z *= scale; v.w *= scale;
        *(float4*)&Qs[d * AQ_S + r4 * 4] = v;
    }

    float m[8], l[8], o[8][5];
#pragma unroll
    for (int i = 0; i < 8; i++) {
        m[i] = -1e30f; l[i] = 0.f;
#pragma unroll
        for (int c = 0; c < 5; c++) o[i][c] = 0.f;
    }

    for (int kt = 0; kt < NN / 128; kt++) {
        __syncthreads();
        // load K tile (d-major, float4 both sides)
        for (int idx = tid; idx < DH * 32; idx += 256) {
            int d = idx >> 5, r4 = idx & 31;
            float4 v = *(const float4*)(K + base_t + (size_t)d * NN + kt * 128 + r4 * 4);
            *(float4*)&Ks[d * AQ_S + r4 * 4] = v;
        }
        // load V tile (row-major float4 gmem, scalar STS into padded rows)
        {
            const float4* Vg = (const float4*)(V + base_v + (size_t)kt * 128 * DH);
            for (int idx = tid; idx < 128 * (DH / 4); idx += 256) {
                int r = idx / (DH / 4), c4 = idx - r * (DH / 4);
                float4 vv = Vg[idx];
                float* dst = &Vs[r * AV_S + c4 * 4];
                dst[0] = vv.x; dst[1] = vv.y; dst[2] = vv.z; dst[3] = vv.w;
            }
        }
        __syncthreads();

        // ---- S = Q K^T : 8x8 register tile (rows ty*8.., cols tx*8..)
        float acc[8][8];
#pragma unroll
        for (int i = 0; i < 8; i++)
#pragma unroll
            for (int j = 0; j < 8; j++) acc[i][j] = 0.f;

#pragma unroll 2
        for (int d = 0; d < DH; d++) {
            float ar[8], br[8];
            *(float4*)(ar)     = *(const float4*)&Qs[d * AQ_S + ty * 8];
            *(float4*)(ar + 4) = *(const float4*)&Qs[d * AQ_S + ty * 8 + 4];
            *(float4*)(br)     = *(const float4*)&Ks[d * AQ_S + tx * 8];
            *(float4*)(br + 4) = *(const float4*)&Ks[d * AQ_S + tx * 8 + 4];
#pragma unroll
            for (int i = 0; i < 8; i++)
#pragma unroll
                for (int j = 0; j < 8; j++)
                    acc[i][j] = fmaf(ar[i], br[j], acc[i][j]);
        }

        // ---- online softmax (row reduce over 16 tx lanes)
        float al[8];
#pragma unroll
        for (int i = 0; i < 8; i++) {
            float tm = acc[i][0];
#pragma unroll
            for (int j = 1; j < 8; j++) tm = fmaxf(tm, acc[i][j]);
#pragma unroll
            for (int off = 1; off < 16; off <<= 1)
                tm = fmaxf(tm, __shfl_xor_sync(0xffffffffu, tm, off));
            float mn = fmaxf(m[i], tm);
            al[i] = __expf(m[i] - mn);
            m[i] = mn;
            float s = 0.f;
#pragma unroll
            for (int j = 0; j < 8; j++) {
                acc[i][j] = __expf(acc[i][j] - mn);
                s += acc[i][j];
            }
#pragma unroll
            for (int off = 1; off < 16; off <<= 1)
                s += __shfl_xor_sync(0xffffffffu, s, off);
            l[i] = l[i] * al[i] + s;
        }

        // write P row-major (float4), rescale O accumulators
#pragma unroll
        for (int i = 0; i < 8; i++) {
            float* srow = &Ss[(ty * 8 + i) * AS_S + tx * 8];
            *(float4*)(srow)     = make_float4(acc[i][0], acc[i][1], acc[i][2], acc[i][3]);
            *(float4*)(srow + 4) = make_float4(acc[i][4], acc[i][5], acc[i][6], acc[i][7]);
#pragma unroll
            for (int c = 0; c < 5; c++) o[i][c] *= al[i];
        }
        __syncthreads();

        // ---- O += P @ V : rows ty*8.. (same as softmax state), cols tx*5..
#pragma unroll 1
        for (int j = 0; j < 128; j += 4) {
            float4 p[8];
#pragma unroll
            for (int i = 0; i < 8; i++)
                p[i] = *(const float4*)&Ss[(ty * 8 + i) * AS_S + j];
#pragma unroll
            for (int u = 0; u < 4; u++) {
                float bv[5];
#pragma unroll
                for (int c = 0; c < 5; c++) bv[c] = Vs[(j + u) * AV_S + tx * 5 + c];
#pragma unroll
                for (int i = 0; i < 8; i++) {
                    float pv = (u == 0) ? p[i].x : (u == 1) ? p[i].y : (u == 2) ? p[i].z : p[i].w;
#pragma unroll
                    for (int c = 0; c < 5; c++)
                        o[i][c] = fmaf(pv, bv[c], o[i][c]);
                }
            }
        }
    }

    // ---- write out (ctx layout [b][n][h*dh]); skip padded cols
    int b = bh >> 4, h = bh & 15;
#pragma unroll
    for (int i = 0; i < 8; i++) {
        float inv = 1.f / l[i];
        size_t orow = ((size_t)(b * NN + q0 + ty * 8 + i) * HH + h) * DH;
#pragma unroll
        for (int c = 0; c < 5; c++) {
            int col = tx * 5 + c;
            if (col < DH) O[orow + col] = o[i][c] * inv;
        }
    }
}

// ---------------------------------------------------------------------------
// launch
// ---------------------------------------------------------------------------
extern "C" void kernel_launch(void* const* d_in, const int* in_sizes, int n_in,
                              void* d_out, int out_size)
{
    const float* x      = (const float*)d_in[0];
    const float* w_qkv  = (const float*)d_in[1];
    const float* w_proj = (const float*)d_in[2];
    const float* b_proj = (const float*)d_in[3];
    const float* qw     = (const float*)d_in[4];
    const float* kw     = (const float*)d_in[5];
    float* out          = (float*)d_out;

    void *p_qkv, *p_q, *p_k, *p_v, *p_ctx;
    cudaGetSymbolAddress(&p_qkv, g_qkv);
    cudaGetSymbolAddress(&p_q, g_q);
    cudaGetSymbolAddress(&p_k, g_k);
    cudaGetSymbolAddress(&p_v, g_v);
    cudaGetSymbolAddress(&p_ctx, g_ctx);
    float* qkv = (float*)p_qkv;
    float* q   = (float*)p_q;
    float* k   = (float*)p_k;
    float* v   = (float*)p_v;
    float* ctx = (float*)p_ctx;

    // 1) QKV GEMM: [8192,1152] x [3456,1152]^T -> [8192,3456]
    {
        dim3 grid(QKVD / 128, MROWS / 128);
        gemm_nt<<<grid, 256>>>(x, w_qkv, nullptr, qkv, MROWS, QKVD, CC);
    }

    // 2a) RoPE + RMSNorm for q,k -> d-major [b][h][dh][n]
    {
        dim3 grid(NN / 32, BB * HH, 2);
        rope_norm_qk<<<grid, 256>>>(qkv, qw, kw);
    }
    // 2b) V copy -> [b][h][n][dh]
    {
        v_split<<<BB * HH * NN / 8, 256>>>(qkv);
    }

    // 3) Flash attention v3 -> ctx in [b][n][h*dh]
    {
        int smem = ATTN3_SMEM_FLOATS * sizeof(float);
        cudaFuncSetAttribute(attn_kernel3, cudaFuncAttributeMaxDynamicSharedMemorySize, smem);
        dim3 grid(NN / 128, BB * HH);
        attn_kernel3<<<grid, 256, smem>>>(q, k, v, ctx);
    }

    // 4) Output projection: [8192,1152] x [1152,1152]^T + bias -> out
    {
        dim3 grid(CC / 128, MROWS / 128);
        gemm_nt<<<grid, 256>>>(ctx, w_proj, b_proj, out, MROWS, CC, CC);
    }
}